// round 1
// baseline (speedup 1.0000x reference)
#include <cuda_runtime.h>
#include <cuda_bf16.h>

#define CC      2048
#define HW      49
#define SIDE    7
#define CGROUPS 8
#define NTHR    512

__global__ __launch_bounds__(NTHR, 2)
void rpcp_kernel(const float* __restrict__ x,
                 const float* __restrict__ Wlin,
                 const float* __restrict__ bias,
                 float* __restrict__ out)
{
    // packed weights per channel: {W1_0[c], W1_1[c], W2_0[c], W2_1[c]}
    __shared__ float4 wsh[CC];
    __shared__ float  acc[CGROUPS][HW][5];
    __shared__ float  fin[HW][5];     // [p]: {sum, a0(W1), a1(W1), d0(W2), d1(W2)}
    __shared__ float  gaps[HW];
    __shared__ float  dls[HW];
    __shared__ int    s_idx;
    __shared__ float  s_gmean;

    const int tid = threadIdx.x;
    const int n   = blockIdx.x;
    const int p   = tid & 63;        // spatial position (0..48 active)
    const int cg  = tid >> 6;        // channel group 0..7

    // Wlin layout: row o of length 2C. W1[o][c]=Wlin[o*2C+c], W2[o][c]=Wlin[o*2C+C+c]
    for (int c = tid; c < CC; c += NTHR) {
        wsh[c] = make_float4(Wlin[c],            // W1_0
                             Wlin[2*CC + c],     // W1_1
                             Wlin[CC + c],       // W2_0
                             Wlin[3*CC + c]);    // W2_1
    }
    __syncthreads();

    float s = 0.f, a0 = 0.f, a1 = 0.f, d0 = 0.f, d1 = 0.f;
    if (p < HW) {
        const float* xp = x + (size_t)n * CC * HW + p;
        #pragma unroll 8
        for (int c = cg; c < CC; c += CGROUPS) {
            float  v = __ldg(xp + (size_t)c * HW);   // coalesced across lanes (consecutive p)
            float4 w = wsh[c];                        // warp-uniform broadcast
            s  += v;
            a0 = fmaf(v, w.x, a0);
            a1 = fmaf(v, w.y, a1);
            d0 = fmaf(v, w.z, d0);
            d1 = fmaf(v, w.w, d1);
        }
        acc[cg][p][0] = s;  acc[cg][p][1] = a0; acc[cg][p][2] = a1;
        acc[cg][p][3] = d0; acc[cg][p][4] = d1;
    }
    __syncthreads();

    // reduce the 8 channel-groups
    if (tid < HW * 5) {
        int pp = tid / 5, k = tid % 5;
        float t = 0.f;
        #pragma unroll
        for (int g = 0; g < CGROUPS; g++) t += acc[g][pp][k];
        fin[pp][k] = t;
    }
    __syncthreads();

    // argmax over channel-mean == argmax over channel-sum (first occurrence on ties)
    if (tid == 0) {
        int best = 0; float bv = fin[0][0];
        #pragma unroll
        for (int q = 1; q < HW; q++) {
            float v = fin[q][0];
            if (v > bv) { bv = v; best = q; }
        }
        s_idx = best;
    }
    __syncthreads();
    const int idx = s_idx;

    if (tid < HW) {
        const float A0 = fin[idx][1];
        const float A1 = fin[idx][2];
        float pr0 = fin[tid][3] + A0 + bias[0];
        float pr1 = fin[tid][4] + A1 + bias[1];
        pr0 = fmaxf(pr0, 0.f);
        pr1 = fmaxf(pr1, 0.f);
        if (tid == idx) { pr0 = 0.f; pr1 = 0.f; }

        const float ri = (float)(tid / SIDE - idx / SIDE) * (1.f / (float)SIDE);
        const float rj = (float)(tid % SIDE - idx % SIDE) * (1.f / (float)SIDE);
        const float rd = sqrtf(ri * ri + rj * rj);
        const float ang = (atan2f(rj, ri) * (1.f / 3.14159265358979323846f) + 1.f) * 0.5f;

        float dl = pr0 - rd; dl *= dl;
        float g  = pr1 - ang;
        if (g < 0.f) g += 1.f;
        gaps[tid] = g;
        dls[tid]  = dl;
    }
    __syncthreads();

    if (tid == 0) {
        float t = 0.f;
        #pragma unroll
        for (int q = 0; q < HW; q++) t += gaps[q];
        s_gmean = t * (1.f / (float)HW);
    }
    __syncthreads();

    if (tid < HW) {
        float g = gaps[tid] - s_gmean;
        out[n * HW + tid] = dls[tid] + g * g;
    }
}

extern "C" void kernel_launch(void* const* d_in, const int* in_sizes, int n_in,
                              void* d_out, int out_size)
{
    const float* x    = (const float*)d_in[0];
    const float* Wlin = (const float*)d_in[1];
    const float* b    = (const float*)d_in[2];
    float*       out  = (float*)d_out;

    const int N = in_sizes[0] / (CC * HW);   // 256
    rpcp_kernel<<<N, NTHR>>>(x, Wlin, b, out);
}